// round 11
// baseline (speedup 1.0000x reference)
#include <cuda_runtime.h>
#include <cuda_bf16.h>
#include <math.h>

// Problem constants
#define BB 2
#define TT 2048
#define CC 768
#define HH 12
#define HD 64
#define D2 32
#define FF 3072
#define MROWS (BB*TT)          // 4096
#define EPSV 1e-5f

// ---------------- scratch ---------------------------------------------------
__device__ float g_h [MROWS*CC];
__device__ float g_q [MROWS*CC];
__device__ float g_k [MROWS*CC];
__device__ float g_v [MROWS*CC];
__device__ float g_y [MROWS*CC];
__device__ float g_x2[MROWS*CC];
__device__ float g_a [MROWS*FF];

// ---------------- helpers ---------------------------------------------------
__device__ __forceinline__ unsigned f2tf(float f) {
    unsigned u;
    asm("cvt.rna.tf32.f32 %0, %1;" : "=r"(u) : "f"(f));
    return u;
}
__device__ __forceinline__ void mma_tf32(float* c, const unsigned* a, const unsigned* b) {
    asm("mma.sync.aligned.m16n8k8.row.col.f32.tf32.tf32.f32 "
        "{%0,%1,%2,%3},{%4,%5,%6,%7},{%8,%9},{%0,%1,%2,%3};"
        : "+f"(c[0]), "+f"(c[1]), "+f"(c[2]), "+f"(c[3])
        : "r"(a[0]), "r"(a[1]), "r"(a[2]), "r"(a[3]), "r"(b[0]), "r"(b[1]));
}
__device__ __forceinline__ void cp_async16(unsigned dst, const void* src) {
    asm volatile("cp.async.cg.shared.global [%0], [%1], 16;" :: "r"(dst), "l"(src));
}
__device__ __forceinline__ void cp_commit() {
    asm volatile("cp.async.commit_group;");
}
template<int N>
__device__ __forceinline__ void cp_wait() {
    asm volatile("cp.async.wait_group %0;" :: "n"(N));
}

// ---------------- RMSNorm ---------------------------------------------------
__global__ void rmsnorm_k(const float* __restrict__ x, const float* __restrict__ g,
                          float* __restrict__ o) {
    int row = blockIdx.x;
    int tid = threadIdx.x;            // 256 threads
    const float* xr = x + (size_t)row * CC;
    float v0 = xr[tid], v1 = xr[tid + 256], v2 = xr[tid + 512];
    float ss = v0*v0 + v1*v1 + v2*v2;
    #pragma unroll
    for (int m = 16; m > 0; m >>= 1) ss += __shfl_xor_sync(0xffffffffu, ss, m);
    __shared__ float ws[8];
    if ((tid & 31) == 0) ws[tid >> 5] = ss;
    __syncthreads();
    float tot = 0.f;
    #pragma unroll
    for (int i = 0; i < 8; i++) tot += ws[i];
    float sc = rsqrtf(tot * (1.0f / CC) + EPSV);
    float* orow = o + (size_t)row * CC;
    orow[tid      ] = g[tid      ] * v0 * sc;
    orow[tid + 256] = g[tid + 256] * v1 * sc;
    orow[tid + 512] = g[tid + 512] * v2 * sc;
}

// ---------------- RoPE in-place, q and k in one launch (y) ------------------
__global__ void rope_k(float* __restrict__ q, float* __restrict__ k,
                       const float* __restrict__ cs, const float* __restrict__ sn) {
    int idx = blockIdx.x * blockDim.x + threadIdx.x;   // over B*T*H*D2
    if (idx >= BB*TT*HH*D2) return;
    float* base = (blockIdx.y == 0) ? q : k;
    int d = idx & (D2 - 1);
    int h = (idx / D2) % HH;
    int t = (idx / (D2 * HH)) % TT;
    int b = idx / (D2 * HH * TT);
    float* p = base + (((size_t)(b*TT + t))*HH + h) * HD;
    float c = cs[t*D2 + d], s = sn[t*D2 + d];
    float x1 = p[d], x2 = p[d + D2];
    p[d]      =  x1 * c + x2 * s;
    p[d + D2] = -x1 * s + x2 * c;
}

// ---------------- TF32 tensor-core GEMM, cp.async 4-stage -------------------
// 256 threads = 8 warps in 2(M) x 4(N); warp tile 64x32; mma.m16n8k8.
// Row-major padded smem; fragments rounded with cvt.rna (tf32) after LDS —
// RZ truncation feeding the MMA directly biases the K=768 dot products
// (measured rel_err 8.3e-4); RNA restores random-walk error (~1.7e-4).
// One __syncthreads per 16-K block; 4-stage cp.async, wait_group 2.
#define AS_STRIDE 20                 // 16 + 4 pad
#define BS_STRIDE 136                // 128 + 8 pad
#define AS_WORDS (128*AS_STRIDE)     // 2560
#define BS_WORDS (16*BS_STRIDE)      // 2176
#define STG_WORDS (AS_WORDS + BS_WORDS)   // 4736
#define GEMM_SMEM (4*STG_WORDS*4)    // 75776 bytes

extern __shared__ float gemm_sm[];

template<int EPI>
__global__ void __launch_bounds__(256, 2)
tfgemm_k(const float* __restrict__ A,
         const float* __restrict__ B0, const float* __restrict__ B1,
         const float* __restrict__ B2,
         float* __restrict__ C0, float* __restrict__ C1, float* __restrict__ C2,
         const float* __restrict__ R, int M, int N, int K) {
    const int tid  = threadIdx.x;
    const int warp = tid >> 5, lane = tid & 31;
    const int wm = warp >> 2, wn = warp & 3;
    const int g = lane >> 2, q = lane & 3;
    const int bm = blockIdx.y * 128, bn = blockIdx.x * 128;
    const float* Bsel = (blockIdx.z == 0) ? B0 : ((blockIdx.z == 1) ? B1 : B2);
    float*       Csel = (blockIdx.z == 0) ? C0 : ((blockIdx.z == 1) ? C1 : C2);
    const float* Ab = A + (size_t)bm * K;
    const float* Bb = Bsel + bn;
    unsigned sbase = (unsigned)__cvta_generic_to_shared(gemm_sm);

    float acc[4][4][4];
    #pragma unroll
    for (int i = 0; i < 4; i++)
        #pragma unroll
        for (int j = 0; j < 4; j++)
            #pragma unroll
            for (int t = 0; t < 4; t++) acc[i][j][t] = 0.f;

    const int NB = K >> 4;            // 48 or 192

    #define ISSUE_STAGE(kb, st)                                                  \
        {                                                                        \
            unsigned sd = sbase + (unsigned)(st)*(STG_WORDS*4u);                 \
            _Pragma("unroll")                                                    \
            for (int it = 0; it < 2; it++) {                                     \
                int idx = it*256 + tid;                                          \
                int m = idx >> 2, k4 = idx & 3;                                  \
                cp_async16(sd + (unsigned)(m*AS_STRIDE + k4*4)*4u,               \
                           Ab + (size_t)m*K + (kb)*16 + k4*4);                   \
                int kr = idx >> 5, n4 = idx & 31;                                \
                cp_async16(sd + (unsigned)(AS_WORDS + kr*BS_STRIDE + n4*4)*4u,   \
                           Bb + (size_t)((kb)*16 + kr)*N + n4*4);                \
            }                                                                    \
            cp_commit();                                                         \
        }

    ISSUE_STAGE(0, 0)
    ISSUE_STAGE(1, 1)
    ISSUE_STAGE(2, 2)

    for (int kb = 0; kb < NB; kb++) {
        cp_wait<2>();                 // stage kb resident
        __syncthreads();              // all warps done with buf (kb+3)&3
        if (kb + 3 < NB) { ISSUE_STAGE(kb + 3, (kb + 3) & 3) }
        const float* As = gemm_sm + (kb & 3)*STG_WORDS;
        const float* Bs = As + AS_WORDS;
        #pragma unroll
        for (int kt = 0; kt < 2; kt++) {
            unsigned a[4][4], b[4][2];
            #pragma unroll
            for (int i = 0; i < 4; i++) {
                const float* ar = As + (wm*64 + i*16)*AS_STRIDE + kt*8;
                a[i][0] = f2tf(ar[(g    )*AS_STRIDE + q    ]);
                a[i][1] = f2tf(ar[(g + 8)*AS_STRIDE + q    ]);
                a[i][2] = f2tf(ar[(g    )*AS_STRIDE + q + 4]);
                a[i][3] = f2tf(ar[(g + 8)*AS_STRIDE + q + 4]);
            }
            #pragma unroll
            for (int j = 0; j < 4; j++) {
                const float* br = Bs + kt*8*BS_STRIDE + wn*32 + j*8 + g;
                b[j][0] = f2tf(br[(q    )*BS_STRIDE]);
                b[j][1] = f2tf(br[(q + 4)*BS_STRIDE]);
            }
            #pragma unroll
            for (int i = 0; i < 4; i++)
                #pragma unroll
                for (int j = 0; j < 4; j++)
                    mma_tf32(acc[i][j], a[i], b[j]);
        }
    }

    // epilogue
    #pragma unroll
    for (int i = 0; i < 4; i++) {
        int r = bm + wm*64 + i*16 + g;
        #pragma unroll
        for (int j = 0; j < 4; j++) {
            int c = bn + wn*32 + j*8 + 2*q;
            float2 v0 = make_float2(acc[i][j][0], acc[i][j][1]);
            float2 v1 = make_float2(acc[i][j][2], acc[i][j][3]);
            if (EPI == 1) {
                float2 rr0 = *(const float2*)(R + (size_t)r*N + c);
                float2 rr1 = *(const float2*)(R + (size_t)(r+8)*N + c);
                v0.x += rr0.x; v0.y += rr0.y;
                v1.x += rr1.x; v1.y += rr1.y;
            } else if (EPI == 2) {
                v0.x = fmaxf(v0.x, 0.f); v0.x *= v0.x;
                v0.y = fmaxf(v0.y, 0.f); v0.y *= v0.y;
                v1.x = fmaxf(v1.x, 0.f); v1.x *= v1.x;
                v1.y = fmaxf(v1.y, 0.f); v1.y *= v1.y;
            }
            *(float2*)(Csel + (size_t)r*N + c)     = v0;
            *(float2*)(Csel + (size_t)(r+8)*N + c) = v1;
        }
    }
    #undef ISSUE_STAGE
}

// ---------------- TF32 tensor-core flash attention, 128-row Q blocks --------
// Block: 128 q rows, 256 threads (8 warps); warp w owns rows w*16..w*16+15.
// K/V tiles of 64 keys double-buffered via cp.async; each K/V load now feeds
// 128 q rows (2x arithmetic intensity vs Round 8). ntiles = 2*qb+2; only the
// last two tiles need causal masking.
#define PADK 68
#define PADV 72
#define KWORDS (64*PADK)            // 4352
#define VWORDS (64*PADV)            // 4608
#define BUFW   (KWORDS + VWORDS)    // 8960
#define ATTN_SMEM (2*BUFW*4)        // 71680 bytes

extern __shared__ float attn_sm[];

__global__ void __launch_bounds__(256)
attn_tc_k(const float* __restrict__ Q, const float* __restrict__ K,
          const float* __restrict__ V, float* __restrict__ Y) {
    const int qb  = blockIdx.x;          // 0..15 (128 q rows each)
    const int bh  = blockIdx.y;
    const int b   = bh / HH, h = bh % HH;
    const int tid = threadIdx.x;
    const int lane = tid & 31, w = tid >> 5;
    const int g = lane >> 2, q = lane & 3;
    const size_t base = (((size_t)b * TT) * HH + h) * HD;
    const float* Qg = Q + base;
    const float* Kg = K + base;
    const float* Vg = V + base;
    unsigned sbase = (unsigned)__cvta_generic_to_shared(attn_sm);

    // ---- stage Q tile (128 x 64) into smem linearly, read A-frags ----------
    // 128*PADK = 8704 words <= 2*BUFW = 17920
    #pragma unroll
    for (int it = 0; it < 8; it++) {
        int idx = it*256 + tid;              // 0..2047
        int r = idx >> 4, c4 = idx & 15;
        cp_async16(sbase + (unsigned)(r*PADK + c4*4)*4u,
                   Qg + (size_t)(qb*128 + r)*(HH*HD) + c4*4);
    }
    cp_commit();
    cp_wait<0>();
    __syncthreads();

    unsigned qa[8][4];
    #pragma unroll
    for (int kf = 0; kf < 8; kf++) {
        qa[kf][0] = __float_as_uint(attn_sm[(w*16 + g    )*PADK + kf*8 + q    ]);
        qa[kf][1] = __float_as_uint(attn_sm[(w*16 + g + 8)*PADK + kf*8 + q    ]);
        qa[kf][2] = __float_as_uint(attn_sm[(w*16 + g    )*PADK + kf*8 + q + 4]);
        qa[kf][3] = __float_as_uint(attn_sm[(w*16 + g + 8)*PADK + kf*8 + q + 4]);
    }
    __syncthreads();

    #define ISSUE_TILE(kb, bufsel)                                              \
        {                                                                       \
            unsigned kd = sbase + (unsigned)(bufsel)*(BUFW*4u);                 \
            _Pragma("unroll")                                                   \
            for (int it = 0; it < 4; it++) {                                    \
                int idx = it*256 + tid;                                         \
                int r = idx >> 4, c4 = idx & 15;                                \
                const float* ksrc = Kg + (size_t)((kb)*64 + r)*(HH*HD) + c4*4;  \
                const float* vsrc = Vg + (size_t)((kb)*64 + r)*(HH*HD) + c4*4;  \
                cp_async16(kd + (unsigned)(r*PADK + c4*4)*4u, ksrc);            \
                cp_async16(kd + (unsigned)(KWORDS + r*PADV + c4*4)*4u, vsrc);   \
            }                                                                   \
            cp_commit();                                                        \
        }

    ISSUE_TILE(0, 0)

    float m0 = -1e30f, m1 = -1e30f, l0 = 0.f, l1 = 0.f;
    float o[8][4];
    #pragma unroll
    for (int nt = 0; nt < 8; nt++)
        #pragma unroll
        for (int t = 0; t < 4; t++) o[nt][t] = 0.f;

    const float scale = 0.125f;   // 1/sqrt(64)
    const int ntiles = 2*qb + 2;
    const int rl0 = qb*128 + w*16 + g;       // global q rows of this thread
    const int rl1 = rl0 + 8;

    for (int kb = 0; kb < ntiles; kb++) {
        cp_wait<0>();
        __syncthreads();           // tile kb visible; prev compute done
        if (kb + 1 < ntiles) { ISSUE_TILE(kb + 1, (kb + 1) & 1) }

        const float* Ks = attn_sm + (kb & 1)*BUFW;
        const float* Vs = Ks + KWORDS;

        // ---- S = Q K^T -----------------------------------------------------
        float s[8][4];
        #pragma unroll
        for (int nt = 0; nt < 8; nt++)
            #pragma unroll
            for (int t = 0; t < 4; t++) s[nt][t] = 0.f;
        #pragma unroll
        for (int kf = 0; kf < 8; kf++) {
            #pragma unroll
            for (int nt = 0; nt < 8; nt++) {
                unsigned bb[2];
                bb[0] = __float_as_uint(Ks[(nt*8 + g)*PADK + kf*8 + q    ]);
                bb[1] = __float_as_uint(Ks[(nt*8 + g)*PADK + kf*8 + q + 4]);
                mma_tf32(s[nt], qa[kf], bb);
            }
        }

        // ---- scale + causal mask (last two tiles only) ---------------------
        #pragma unroll
        for (int nt = 0; nt < 8; nt++) {
            s[nt][0] *= scale; s[nt][1] *= scale;
            s[nt][2] *= scale; s[nt][3] *= scale;
        }
        if (kb >= 2*qb) {
            #pragma unroll
            for (int nt = 0; nt < 8; nt++) {
                int c0 = kb*64 + nt*8 + 2*q, c1 = c0 + 1;
                if (c0 > rl0) s[nt][0] = -1e30f;
                if (c1 > rl0) s[nt][1] = -1e30f;
                if (c0 > rl1) s[nt][2] = -1e30f;
                if (c1 > rl1) s[nt][3] = -1e30f;
            }
        }

        // ---- online softmax ------------------------------------------------
        float tm0 = -1e30f, tm1 = -1e30f;
        #pragma unroll
        for (int nt = 0; nt < 8; nt++) {
            tm0 = fmaxf(tm0, fmaxf(s[nt][0], s[nt][1]));
            tm1 = fmaxf(tm1, fmaxf(s[nt][2], s[nt][3]));
        }
        tm0 = fmaxf(tm0, __shfl_xor_sync(0xffffffffu, tm0, 1));
        tm0 = fmaxf(tm0, __shfl_xor_sync(0xffffffffu, tm0, 2));
        tm1 = fmaxf(tm1, __shfl_xor_sync(0xffffffffu, tm1, 1));
        tm1 = fmaxf(tm1, __shfl_xor_sync(0xffffffffu, tm1, 2));
        float mn0 = fmaxf(m0, tm0), mn1 = fmaxf(m1, tm1);
        float f0 = __expf(m0 - mn0), f1 = __expf(m1 - mn1);
        m0 = mn0; m1 = mn1;
        float sum0 = 0.f, sum1 = 0.f;
        #pragma unroll
        for (int nt = 0; nt < 8; nt++) {
            s[nt][0] = __expf(s[nt][0] - mn0); sum0 += s[nt][0];
            s[nt][1] = __expf(s[nt][1] - mn0); sum0 += s[nt][1];
            s[nt][2] = __expf(s[nt][2] - mn1); sum1 += s[nt][2];
            s[nt][3] = __expf(s[nt][3] - mn1); sum1 += s[nt][3];
        }
        sum0 += __shfl_xor_sync(0xffffffffu, sum0, 1);
        sum0 += __shfl_xor_sync(0xffffffffu, sum0, 2);
        sum1 += __shfl_xor_sync(0xffffffffu, sum1, 1);
        sum1 += __shfl_xor_sync(0xffffffffu, sum1, 2);
        l0 = l0*f0 + sum0;
        l1 = l1*f1 + sum1;
        #pragma unroll
        for (int nt = 0; nt < 8; nt++) {
            o[nt][0] *= f0; o[nt][1] *= f0;
            o[nt][2] *= f1; o[nt][3] *= f1;
        }

        // ---- O += P V : P C-frag -> A-frag via quad shuffles ---------------
        #pragma unroll
        for (int kf = 0; kf < 8; kf++) {
            int src0 = (lane & ~3) | (q >> 1);
            float v00 = __shfl_sync(0xffffffffu, s[kf][0], src0);
            float v01 = __shfl_sync(0xffffffffu, s[kf][1], src0);
            float v10 = __shfl_sync(0xffffffffu, s[kf][2], src0);
            float v11 = __shfl_sync(0xffffffffu, s[kf][3], src0);
            float v20 = __shfl_sync(0xffffffffu, s[kf][0], src0 + 2);
            float v21 = __shfl_sync(0xffffffffu, s[kf][1], src0 + 2);
            float v30 = __shfl_sync(0xffffffffu, s[kf][2], src0 + 2);
            float v31 = __shfl_sync(0xffffffffu, s[kf][3], src0 + 2);
            unsigned pa[4];
            pa[0] = __float_as_uint((q & 1) ? v01 : v00);
            pa[1] = __float_as_uint((q & 1) ? v11 : v10);
            pa[2] = __float_as_uint((q & 1) ? v21 : v20);
            pa[3] = __float_as_uint((q & 1) ? v31 : v30);
            #pragma unroll
            for (int nt = 0; nt < 8; nt++) {
                unsigned vb[2];
                vb[0] = __float_as_uint(Vs[(kf*8 + q    )*PADV + nt*8 + g]);
                vb[1] = __float_as_uint(Vs[(kf*8 + q + 4)*PADV + nt*8 + g]);
                mma_tf32(o[nt], pa, vb);
            }
        }
    }

    // ---- epilogue ----------------------------------------------------------
    float inv0 = 1.0f / l0, inv1 = 1.0f / l1;
    #pragma unroll
    for (int nt = 0; nt < 8; nt++) {
        float2 v0 = make_float2(o[nt][0]*inv0, o[nt][1]*inv0);
        float2 v1 = make_float2(o[nt][2]*inv1, o[nt][3]*inv1);
        *(float2*)(Y + base + (size_t)rl0*(HH*HD) + nt*8 + 2*q) = v0;
        *(float2*)(Y + base + (size_t)rl1*(HH*HD) + nt*8 + 2*q) = v1;
    }
    #undef ISSUE_TILE
}

// ---------------- launch ----------------------------------------------------
extern "C" void kernel_launch(void* const* d_in, const int* in_sizes, int n_in,
                              void* d_out, int out_size) {
    const float* x   = (const float*)d_in[0];
    const float* cs  = (const float*)d_in[1];
    const float* sn  = (const float*)d_in[2];
    const float* wq  = (const float*)d_in[3];
    const float* wk  = (const float*)d_in[4];
    const float* wv  = (const float*)d_in[5];
    const float* wo  = (const float*)d_in[6];
    const float* wfc = (const float*)d_in[7];
    const float* wpr = (const float*)d_in[8];
    const float* g1  = (const float*)d_in[9];
    const float* g2  = (const float*)d_in[10];
    float* out = (float*)d_out;

    float *h_, *q_, *k_, *v_, *y_, *x2_, *a_;
    cudaGetSymbolAddress((void**)&h_,  g_h);
    cudaGetSymbolAddress((void**)&q_,  g_q);
    cudaGetSymbolAddress((void**)&k_,  g_k);
    cudaGetSymbolAddress((void**)&v_,  g_v);
    cudaGetSymbolAddress((void**)&y_,  g_y);
    cudaGetSymbolAddress((void**)&x2_, g_x2);
    cudaGetSymbolAddress((void**)&a_,  g_a);

    cudaFuncSetAttribute(attn_tc_k, cudaFuncAttributeMaxDynamicSharedMemorySize,
                         ATTN_SMEM);
    cudaFuncSetAttribute(tfgemm_k<0>, cudaFuncAttributeMaxDynamicSharedMemorySize,
                         GEMM_SMEM);
    cudaFuncSetAttribute(tfgemm_k<1>, cudaFuncAttributeMaxDynamicSharedMemorySize,
                         GEMM_SMEM);
    cudaFuncSetAttribute(tfgemm_k<2>, cudaFuncAttributeMaxDynamicSharedMemorySize,
                         GEMM_SMEM);

    dim3 gemm_qkv(CC/128, MROWS/128, 3);  // (6, 32, 3) fused QKV
    dim3 gemm_cc (CC/128, MROWS/128, 1);  // (6, 32)
    dim3 gemm_ff (FF/128, MROWS/128, 1);  // (24, 32)

    // 1. h = rmsnorm(x, g1)
    rmsnorm_k<<<MROWS, 256>>>(x, g1, h_);
    // 2. q,k,v = h @ w{q,k,v}  (one fused launch)
    tfgemm_k<0><<<gemm_qkv, 256, GEMM_SMEM>>>(h_, wq, wk, wv, q_, k_, v_, nullptr, MROWS, CC, CC);
    // 3. RoPE on q and k (one launch)
    int nrope = BB*TT*HH*D2;
    rope_k<<<dim3((nrope + 255)/256, 2), 256>>>(q_, k_, cs, sn);
    // 4. attention -> y [B,T,H,HD]  (tensor-core flash, 128-row q blocks)
    attn_tc_k<<<dim3(TT/128, BB*HH), 256, ATTN_SMEM>>>(q_, k_, v_, y_);
    // 5. x2 = x + y @ wo
    tfgemm_k<1><<<gemm_cc, 256, GEMM_SMEM>>>(y_, wo, wo, wo, x2_, x2_, x2_, x, MROWS, CC, CC);
    // 6. h = rmsnorm(x2, g2)
    rmsnorm_k<<<MROWS, 256>>>(x2_, g2, h_);
    // 7. a = relu(h @ wfc)^2
    tfgemm_k<2><<<gemm_ff, 256, GEMM_SMEM>>>(h_, wfc, wfc, wfc, a_, a_, a_, nullptr, MROWS, FF, CC);
    // 8. out = x2 + a @ wpr
    tfgemm_k<1><<<gemm_cc, 256, GEMM_SMEM>>>(a_, wpr, wpr, wpr, out, out, out, x2_, MROWS, CC, FF);
}

// round 13
// speedup vs baseline: 1.0970x; 1.0970x over previous
#include <cuda_runtime.h>
#include <cuda_bf16.h>
#include <math.h>

// Problem constants
#define BB 2
#define TT 2048
#define CC 768
#define HH 12
#define HD 64
#define D2 32
#define FF 3072
#define MROWS (BB*TT)          // 4096
#define EPSV 1e-5f

// ---------------- scratch ---------------------------------------------------
__device__ float g_h [MROWS*CC];
__device__ float g_q [MROWS*CC];
__device__ float g_k [MROWS*CC];
__device__ float g_v [MROWS*CC];
__device__ float g_y [MROWS*CC];
__device__ float g_x2[MROWS*CC];
__device__ float g_a [MROWS*FF];
// rounded weights: wq | wk | wv | wo | wfc | wpr
#define WCC (CC*CC)               // 589824
#define WFF (CC*FF)               // 2359296
#define W_OFF_FC (4*WCC)
#define W_OFF_PR (4*WCC + WFF)
__device__ float g_w [4*WCC + 2*WFF];   // 7077888 floats

// ---------------- helpers ---------------------------------------------------
__device__ __forceinline__ unsigned f2tf(float f) {
    unsigned u;
    asm("cvt.rna.tf32.f32 %0, %1;" : "=r"(u) : "f"(f));
    return u;
}
__device__ __forceinline__ float roundtf(float f) {
    return __uint_as_float(f2tf(f));
}
__device__ __forceinline__ void mma_tf32(float* c, const unsigned* a, const unsigned* b) {
    asm("mma.sync.aligned.m16n8k8.row.col.f32.tf32.tf32.f32 "
        "{%0,%1,%2,%3},{%4,%5,%6,%7},{%8,%9},{%0,%1,%2,%3};"
        : "+f"(c[0]), "+f"(c[1]), "+f"(c[2]), "+f"(c[3])
        : "r"(a[0]), "r"(a[1]), "r"(a[2]), "r"(a[3]), "r"(b[0]), "r"(b[1]));
}
__device__ __forceinline__ void cp_async16(unsigned dst, const void* src) {
    asm volatile("cp.async.cg.shared.global [%0], [%1], 16;" :: "r"(dst), "l"(src));
}
__device__ __forceinline__ void cp_commit() {
    asm volatile("cp.async.commit_group;");
}
template<int N>
__device__ __forceinline__ void cp_wait() {
    asm volatile("cp.async.wait_group %0;" :: "n"(N));
}

// ---------------- weight pre-round (tf32 RNA) --------------------------------
// After this, GEMMs can feed raw fp32 bits to mma: RZ truncation of an
// already-RNA-rounded value is the identity, so inner loops carry zero
// rounding cost with full RNA accuracy.
__global__ void preround4_k(const float* __restrict__ w0, const float* __restrict__ w1,
                            const float* __restrict__ w2, const float* __restrict__ w3,
                            float* __restrict__ dst) {
    int i = blockIdx.x * blockDim.x + threadIdx.x;      // over WCC/4
    const float* s = (blockIdx.y == 0) ? w0 : (blockIdx.y == 1) ? w1
                   : (blockIdx.y == 2) ? w2 : w3;
    float4 v = ((const float4*)s)[i];
    v.x = roundtf(v.x); v.y = roundtf(v.y); v.z = roundtf(v.z); v.w = roundtf(v.w);
    ((float4*)(dst + (size_t)blockIdx.y * WCC))[i] = v;
}
__global__ void preround_k(const float* __restrict__ s, float* __restrict__ d) {
    int i = blockIdx.x * blockDim.x + threadIdx.x;      // over WFF/4
    float4 v = ((const float4*)s)[i];
    v.x = roundtf(v.x); v.y = roundtf(v.y); v.z = roundtf(v.z); v.w = roundtf(v.w);
    ((float4*)d)[i] = v;
}

// ---------------- RMSNorm (output tf32-rounded) ------------------------------
__global__ void rmsnorm_k(const float* __restrict__ x, const float* __restrict__ g,
                          float* __restrict__ o) {
    int row = blockIdx.x;
    int tid = threadIdx.x;            // 256 threads
    const float* xr = x + (size_t)row * CC;
    float v0 = xr[tid], v1 = xr[tid + 256], v2 = xr[tid + 512];
    float ss = v0*v0 + v1*v1 + v2*v2;
    #pragma unroll
    for (int m = 16; m > 0; m >>= 1) ss += __shfl_xor_sync(0xffffffffu, ss, m);
    __shared__ float ws[8];
    if ((tid & 31) == 0) ws[tid >> 5] = ss;
    __syncthreads();
    float tot = 0.f;
    #pragma unroll
    for (int i = 0; i < 8; i++) tot += ws[i];
    float sc = rsqrtf(tot * (1.0f / CC) + EPSV);
    float* orow = o + (size_t)row * CC;
    orow[tid      ] = roundtf(g[tid      ] * v0 * sc);
    orow[tid + 256] = roundtf(g[tid + 256] * v1 * sc);
    orow[tid + 512] = roundtf(g[tid + 512] * v2 * sc);
}

// ---------------- RoPE in-place (output tf32-rounded) ------------------------
__global__ void rope_k(float* __restrict__ q, float* __restrict__ k,
                       const float* __restrict__ cs, const float* __restrict__ sn) {
    int idx = blockIdx.x * blockDim.x + threadIdx.x;   // over B*T*H*D2
    if (idx >= BB*TT*HH*D2) return;
    float* base = (blockIdx.y == 0) ? q : k;
    int d = idx & (D2 - 1);
    int h = (idx / D2) % HH;
    int t = (idx / (D2 * HH)) % TT;
    int b = idx / (D2 * HH * TT);
    float* p = base + (((size_t)(b*TT + t))*HH + h) * HD;
    float c = cs[t*D2 + d], s = sn[t*D2 + d];
    float x1 = p[d], x2 = p[d + D2];
    p[d]      = roundtf( x1 * c + x2 * s);
    p[d + D2] = roundtf(-x1 * s + x2 * c);
}

// ---------------- TF32 tensor-core GEMM, cp.async 3-stage -------------------
// Round-10 configuration (fastest measured): raw fp32 bits fed as tf32.
// All A/B inputs are pre-rounded at producers -> exact RNA semantics.
// EPI: 0 = plain (rounded out), 1 = +residual R (full fp32 out),
//      2 = relu(x)^2 (rounded out)
#define AS_STRIDE 20                 // 16 + 4 pad
#define BS_STRIDE 136                // 128 + 8 pad
#define AS_WORDS (128*AS_STRIDE)     // 2560
#define BS_WORDS (16*BS_STRIDE)      // 2176
#define STG_WORDS (AS_WORDS + BS_WORDS)   // 4736
#define GEMM_SMEM (3*STG_WORDS*4)    // 56832 bytes

extern __shared__ float gemm_sm[];

template<int EPI>
__global__ void __launch_bounds__(256, 2)
tfgemm_k(const float* __restrict__ A,
         const float* __restrict__ B0, const float* __restrict__ B1,
         const float* __restrict__ B2,
         float* __restrict__ C0, float* __restrict__ C1, float* __restrict__ C2,
         const float* __restrict__ R, int M, int N, int K) {
    const int tid  = threadIdx.x;
    const int warp = tid >> 5, lane = tid & 31;
    const int wm = warp >> 2, wn = warp & 3;
    const int g = lane >> 2, q = lane & 3;
    const int bm = blockIdx.y * 128, bn = blockIdx.x * 128;
    const float* Bsel = (blockIdx.z == 0) ? B0 : ((blockIdx.z == 1) ? B1 : B2);
    float*       Csel = (blockIdx.z == 0) ? C0 : ((blockIdx.z == 1) ? C1 : C2);
    const float* Ab = A + (size_t)bm * K;
    const float* Bb = Bsel + bn;
    unsigned sbase = (unsigned)__cvta_generic_to_shared(gemm_sm);

    float acc[4][4][4];
    #pragma unroll
    for (int i = 0; i < 4; i++)
        #pragma unroll
        for (int j = 0; j < 4; j++)
            #pragma unroll
            for (int t = 0; t < 4; t++) acc[i][j][t] = 0.f;

    const int NB = K >> 4;            // 48 or 192

    #define ISSUE_STAGE(kb, st)                                                  \
        {                                                                        \
            unsigned sd = sbase + (unsigned)(st)*(STG_WORDS*4u);                 \
            _Pragma("unroll")                                                    \
            for (int it = 0; it < 2; it++) {                                     \
                int idx = it*256 + tid;                                          \
                int m = idx >> 2, k4 = idx & 3;                                  \
                cp_async16(sd + (unsigned)(m*AS_STRIDE + k4*4)*4u,               \
                           Ab + (size_t)m*K + (kb)*16 + k4*4);                   \
                int kr = idx >> 5, n4 = idx & 31;                                \
                cp_async16(sd + (unsigned)(AS_WORDS + kr*BS_STRIDE + n4*4)*4u,   \
                           Bb + (size_t)((kb)*16 + kr)*N + n4*4);                \
            }                                                                    \
            cp_commit();                                                         \
        }

    ISSUE_STAGE(0, 0)
    ISSUE_STAGE(1, 1)

    int st = 0;
    for (int kb = 0; kb < NB; kb++) {
        cp_wait<1>();                 // stage kb resident
        __syncthreads();              // all warps past compute kb-1
        if (kb + 2 < NB) {
            int st2 = st + 2; if (st2 >= 3) st2 -= 3;
            ISSUE_STAGE(kb + 2, st2)
        }
        const float* As = gemm_sm + st*STG_WORDS;
        const float* Bs = As + AS_WORDS;
        #pragma unroll
        for (int kt = 0; kt < 2; kt++) {
            unsigned a[4][4], b[4][2];
            #pragma unroll
            for (int i = 0; i < 4; i++) {
                const float* ar = As + (wm*64 + i*16)*AS_STRIDE + kt*8;
                a[i][0] = __float_as_uint(ar[(g    )*AS_STRIDE + q    ]);
                a[i][1] = __float_as_uint(ar[(g + 8)*AS_STRIDE + q    ]);
                a[i][2] = __float_as_uint(ar[(g    )*AS_STRIDE + q + 4]);
                a[i][3] = __float_as_uint(ar[(g + 8)*AS_STRIDE + q + 4]);
            }
            #pragma unroll
            for (int j = 0; j < 4; j++) {
                const float* br = Bs + kt*8*BS_STRIDE + wn*32 + j*8 + g;
                b[j][0] = __float_as_uint(br[(q    )*BS_STRIDE]);
                b[j][1] = __float_as_uint(br[(q + 4)*BS_STRIDE]);
            }
            #pragma unroll
            for (int i = 0; i < 4; i++)
                #pragma unroll
                for (int j = 0; j < 4; j++)
                    mma_tf32(acc[i][j], a[i], b[j]);
        }
        st++; if (st >= 3) st = 0;
    }

    // epilogue
    #pragma unroll
    for (int i = 0; i < 4; i++) {
        int r = bm + wm*64 + i*16 + g;
        #pragma unroll
        for (int j = 0; j < 4; j++) {
            int c = bn + wn*32 + j*8 + 2*q;
            float2 v0 = make_float2(acc[i][j][0], acc[i][j][1]);
            float2 v1 = make_float2(acc[i][j][2], acc[i][j][3]);
            if (EPI == 1) {
                float2 rr0 = *(const float2*)(R + (size_t)r*N + c);
                float2 rr1 = *(const float2*)(R + (size_t)(r+8)*N + c);
                v0.x += rr0.x; v0.y += rr0.y;
                v1.x += rr1.x; v1.y += rr1.y;
            } else if (EPI == 2) {
                v0.x = fmaxf(v0.x, 0.f); v0.x = roundtf(v0.x * v0.x);
                v0.y = fmaxf(v0.y, 0.f); v0.y = roundtf(v0.y * v0.y);
                v1.x = fmaxf(v1.x, 0.f); v1.x = roundtf(v1.x * v1.x);
                v1.y = fmaxf(v1.y, 0.f); v1.y = roundtf(v1.y * v1.y);
            } else {   // EPI == 0: q/k/v -> round for downstream MMA use
                v0.x = roundtf(v0.x); v0.y = roundtf(v0.y);
                v1.x = roundtf(v1.x); v1.y = roundtf(v1.y);
            }
            *(float2*)(Csel + (size_t)r*N + c)     = v0;
            *(float2*)(Csel + (size_t)(r+8)*N + c) = v1;
        }
    }
    #undef ISSUE_STAGE
}

// ---------------- TF32 tensor-core flash attention, 128-row Q blocks --------
#define PADK 68
#define PADV 72
#define KWORDS (64*PADK)            // 4352
#define VWORDS (64*PADV)            // 4608
#define BUFW   (KWORDS + VWORDS)    // 8960
#define ATTN_SMEM (2*BUFW*4)        // 71680 bytes

extern __shared__ float attn_sm[];

__global__ void __launch_bounds__(256)
attn_tc_k(const float* __restrict__ Q, const float* __restrict__ K,
          const float* __restrict__ V, float* __restrict__ Y) {
    const int qb  = blockIdx.x;          // 0..15 (128 q rows each)
    const int bh  = blockIdx.y;
    const int b   = bh / HH, h = bh % HH;
    const int tid = threadIdx.x;
    const int lane = tid & 31, w = tid >> 5;
    const int g = lane >> 2, q = lane & 3;
    const size_t base = (((size_t)b * TT) * HH + h) * HD;
    const float* Qg = Q + base;
    const float* Kg = K + base;
    const float* Vg = V + base;
    unsigned sbase = (unsigned)__cvta_generic_to_shared(attn_sm);

    // ---- stage Q tile (128 x 64) into smem, read A-frags --------------------
    #pragma unroll
    for (int it = 0; it < 8; it++) {
        int idx = it*256 + tid;              // 0..2047
        int r = idx >> 4, c4 = idx & 15;
        cp_async16(sbase + (unsigned)(r*PADK + c4*4)*4u,
                   Qg + (size_t)(qb*128 + r)*(HH*HD) + c4*4);
    }
    cp_commit();
    cp_wait<0>();
    __syncthreads();

    unsigned qa[8][4];
    #pragma unroll
    for (int kf = 0; kf < 8; kf++) {
        qa[kf][0] = __float_as_uint(attn_sm[(w*16 + g    )*PADK + kf*8 + q    ]);
        qa[kf][1] = __float_as_uint(attn_sm[(w*16 + g + 8)*PADK + kf*8 + q    ]);
        qa[kf][2] = __float_as_uint(attn_sm[(w*16 + g    )*PADK + kf*8 + q + 4]);
        qa[kf][3] = __float_as_uint(attn_sm[(w*16 + g + 8)*PADK + kf*8 + q + 4]);
    }
    __syncthreads();

    #define ISSUE_TILE(kb, bufsel)                                              \
        {                                                                       \
            unsigned kd = sbase + (unsigned)(bufsel)*(BUFW*4u);                 \
            _Pragma("unroll")                                                   \
            for (int it = 0; it < 4; it++) {                                    \
                int idx = it*256 + tid;                                         \
                int r = idx >> 4, c4 = idx & 15;                                \
                const float* ksrc = Kg + (size_t)((kb)*64 + r)*(HH*HD) + c4*4;  \
                const float* vsrc = Vg + (size_t)((kb)*64 + r)*(HH*HD) + c4*4;  \
                cp_async16(kd + (unsigned)(r*PADK + c4*4)*4u, ksrc);            \
                cp_async16(kd + (unsigned)(KWORDS + r*PADV + c4*4)*4u, vsrc);   \
            }                                                                   \
            cp_commit();                                                        \
        }

    ISSUE_TILE(0, 0)

    float m0 = -1e30f, m1 = -1e30f, l0 = 0.f, l1 = 0.f;
    float o[8][4];
    #pragma unroll
    for (int nt = 0; nt < 8; nt++)
        #pragma unroll
        for (int t = 0; t < 4; t++) o[nt][t] = 0.f;

    const float scale = 0.125f;   // 1/sqrt(64)
    const int ntiles = 2*qb + 2;
    const int rl0 = qb*128 + w*16 + g;       // global q rows of this thread
    const int rl1 = rl0 + 8;

    for (int kb = 0; kb < ntiles; kb++) {
        cp_wait<0>();
        __syncthreads();           // tile kb visible; prev compute done
        if (kb + 1 < ntiles) { ISSUE_TILE(kb + 1, (kb + 1) & 1) }

        const float* Ks = attn_sm + (kb & 1)*BUFW;
        const float* Vs = Ks + KWORDS;

        // ---- S = Q K^T -----------------------------------------------------
        float s[8][4];
        #pragma unroll
        for (int nt = 0; nt < 8; nt++)
            #pragma unroll
            for (int t = 0; t < 4; t++) s[nt][t] = 0.f;
        #pragma unroll
        for (int kf = 0; kf < 8; kf++) {
            #pragma unroll
            for (int nt = 0; nt < 8; nt++) {
                unsigned bb[2];
                bb[0] = __float_as_uint(Ks[(nt*8 + g)*PADK + kf*8 + q    ]);
                bb[1] = __float_as_uint(Ks[(nt*8 + g)*PADK + kf*8 + q + 4]);
                mma_tf32(s[nt], qa[kf], bb);
            }
        }

        // ---- scale + causal mask (last two tiles only) ---------------------
        #pragma unroll
        for (int nt = 0; nt < 8; nt++) {
            s[nt][0] *= scale; s[nt][1] *= scale;
            s[nt][2] *= scale; s[nt][3] *= scale;
        }
        if (kb >= 2*qb) {
            #pragma unroll
            for (int nt = 0; nt < 8; nt++) {
                int c0 = kb*64 + nt*8 + 2*q, c1 = c0 + 1;
                if (c0 > rl0) s[nt][0] = -1e30f;
                if (c1 > rl0) s[nt][1] = -1e30f;
                if (c0 > rl1) s[nt][2] = -1e30f;
                if (c1 > rl1) s[nt][3] = -1e30f;
            }
        }

        // ---- online softmax ------------------------------------------------
        float tm0 = -1e30f, tm1 = -1e30f;
        #pragma unroll
        for (int nt = 0; nt < 8; nt++) {
            tm0 = fmaxf(tm0, fmaxf(s[nt][0], s[nt][1]));
            tm1 = fmaxf(tm1, fmaxf(s[nt][2], s[nt][3]));
        }
        tm0 = fmaxf(tm0, __shfl_xor_sync(0xffffffffu, tm0, 1));
        tm0 = fmaxf(tm0, __shfl_xor_sync(0xffffffffu, tm0, 2));
        tm1 = fmaxf(tm1, __shfl_xor_sync(0xffffffffu, tm1, 1));
        tm1 = fmaxf(tm1, __shfl_xor_sync(0xffffffffu, tm1, 2));
        float mn0 = fmaxf(m0, tm0), mn1 = fmaxf(m1, tm1);
        float f0 = __expf(m0 - mn0), f1 = __expf(m1 - mn1);
        m0 = mn0; m1 = mn1;
        float sum0 = 0.f, sum1 = 0.f;
        #pragma unroll
        for (int nt = 0; nt < 8; nt++) {
            s[nt][0] = __expf(s[nt][0] - mn0); sum0 += s[nt][0];
            s[nt][1] = __expf(s[nt][1] - mn0); sum0 += s[nt][1];
            s[nt][2] = __expf(s[nt][2] - mn1); sum1 += s[nt][2];
            s[nt][3] = __expf(s[nt][3] - mn1); sum1 += s[nt][3];
        }
        sum0 += __shfl_xor_sync(0xffffffffu, sum0, 1);
        sum0 += __shfl_xor_sync(0xffffffffu, sum0, 2);
        sum1 += __shfl_xor_sync(0xffffffffu, sum1, 1);
        sum1 += __shfl_xor_sync(0xffffffffu, sum1, 2);
        l0 = l0*f0 + sum0;
        l1 = l1*f1 + sum1;
        #pragma unroll
        for (int nt = 0; nt < 8; nt++) {
            o[nt][0] *= f0; o[nt][1] *= f0;
            o[nt][2] *= f1; o[nt][3] *= f1;
        }

        // ---- O += P V : P C-frag -> A-frag via quad shuffles ---------------
        #pragma unroll
        for (int kf = 0; kf < 8; kf++) {
            int src0 = (lane & ~3) | (q >> 1);
            float v00 = __shfl_sync(0xffffffffu, s[kf][0], src0);
            float v01 = __shfl_sync(0xffffffffu, s[kf][1], src0);
            float v10 = __shfl_sync(0xffffffffu, s[kf][2], src0);
            float v11 = __shfl_sync(0xffffffffu, s[kf][3], src0);
            float v20 = __shfl_sync(0xffffffffu, s[kf][0], src0 + 2);
            float v21 = __shfl_sync(0xffffffffu, s[kf][1], src0 + 2);
            float v30 = __shfl_sync(0xffffffffu, s[kf][2], src0 + 2);
            float v31 = __shfl_sync(0xffffffffu, s[kf][3], src0 + 2);
            unsigned pa[4];
            pa[0] = __float_as_uint((q & 1) ? v01 : v00);
            pa[1] = __float_as_uint((q & 1) ? v11 : v10);
            pa[2] = __float_as_uint((q & 1) ? v21 : v20);
            pa[3] = __float_as_uint((q & 1) ? v31 : v30);
            #pragma unroll
            for (int nt = 0; nt < 8; nt++) {
                unsigned vb[2];
                vb[0] = __float_as_uint(Vs[(kf*8 + q    )*PADV + nt*8 + g]);
                vb[1] = __float_as_uint(Vs[(kf*8 + q + 4)*PADV + nt*8 + g]);
                mma_tf32(o[nt], pa, vb);
            }
        }
    }

    // ---- epilogue (round y for the wo GEMM) --------------------------------
    float inv0 = 1.0f / l0, inv1 = 1.0f / l1;
    #pragma unroll
    for (int nt = 0; nt < 8; nt++) {
        float2 v0 = make_float2(roundtf(o[nt][0]*inv0), roundtf(o[nt][1]*inv0));
        float2 v1 = make_float2(roundtf(o[nt][2]*inv1), roundtf(o[nt][3]*inv1));
        *(float2*)(Y + base + (size_t)rl0*(HH*HD) + nt*8 + 2*q) = v0;
        *(float2*)(Y + base + (size_t)rl1*(HH*HD) + nt*8 + 2*q) = v1;
    }
    #undef ISSUE_TILE
}

// ---------------- launch ----------------------------------------------------
extern "C" void kernel_launch(void* const* d_in, const int* in_sizes, int n_in,
                              void* d_out, int out_size) {
    const float* x   = (const float*)d_in[0];
    const float* cs  = (const float*)d_in[1];
    const float* sn  = (const float*)d_in[2];
    const float* wq  = (const float*)d_in[3];
    const float* wk  = (const float*)d_in[4];
    const float* wv  = (const float*)d_in[5];
    const float* wo  = (const float*)d_in[6];
    const float* wfc = (const float*)d_in[7];
    const float* wpr = (const float*)d_in[8];
    const float* g1  = (const float*)d_in[9];
    const float* g2  = (const float*)d_in[10];
    float* out = (float*)d_out;

    float *h_, *q_, *k_, *v_, *y_, *x2_, *a_, *w_;
    cudaGetSymbolAddress((void**)&h_,  g_h);
    cudaGetSymbolAddress((void**)&q_,  g_q);
    cudaGetSymbolAddress((void**)&k_,  g_k);
    cudaGetSymbolAddress((void**)&v_,  g_v);
    cudaGetSymbolAddress((void**)&y_,  g_y);
    cudaGetSymbolAddress((void**)&x2_, g_x2);
    cudaGetSymbolAddress((void**)&a_,  g_a);
    cudaGetSymbolAddress((void**)&w_,  g_w);

    cudaFuncSetAttribute(attn_tc_k, cudaFuncAttributeMaxDynamicSharedMemorySize,
                         ATTN_SMEM);
    cudaFuncSetAttribute(tfgemm_k<0>, cudaFuncAttributeMaxDynamicSharedMemorySize,
                         GEMM_SMEM);
    cudaFuncSetAttribute(tfgemm_k<1>, cudaFuncAttributeMaxDynamicSharedMemorySize,
                         GEMM_SMEM);
    cudaFuncSetAttribute(tfgemm_k<2>, cudaFuncAttributeMaxDynamicSharedMemorySize,
                         GEMM_SMEM);

    const float* rwq  = w_;
    const float* rwk  = w_ +   WCC;
    const float* rwv  = w_ + 2*WCC;
    const float* rwo  = w_ + 3*WCC;
    const float* rwfc = w_ + W_OFF_FC;
    const float* rwpr = w_ + W_OFF_PR;

    dim3 gemm_qkv(CC/128, MROWS/128, 3);  // (6, 32, 3) fused QKV
    dim3 gemm_cc (CC/128, MROWS/128, 1);  // (6, 32)
    dim3 gemm_ff (FF/128, MROWS/128, 1);  // (24, 32)

    // 0. pre-round weights to tf32 (RNA) once per launch
    preround4_k<<<dim3(WCC/4/256, 4), 256>>>(wq, wk, wv, wo, (float*)w_);
    preround_k<<<WFF/4/256, 256>>>(wfc, (float*)rwfc);
    preround_k<<<WFF/4/256, 256>>>(wpr, (float*)rwpr);
    // 1. h = rmsnorm(x, g1)   (rounded)
    rmsnorm_k<<<MROWS, 256>>>(x, g1, h_);
    // 2. q,k,v = h @ w{q,k,v}  (one fused launch; rounded outputs)
    tfgemm_k<0><<<gemm_qkv, 256, GEMM_SMEM>>>(h_, rwq, rwk, rwv, q_, k_, v_, nullptr, MROWS, CC, CC);
    // 3. RoPE on q and k (rounded outputs)
    int nrope = BB*TT*HH*D2;
    rope_k<<<dim3((nrope + 255)/256, 2), 256>>>(q_, k_, cs, sn);
    // 4. attention -> y (rounded)
    attn_tc_k<<<dim3(TT/128, BB*HH), 256, ATTN_SMEM>>>(q_, k_, v_, y_);
    // 5. x2 = x + y @ wo   (full fp32)
    tfgemm_k<1><<<gemm_cc, 256, GEMM_SMEM>>>(y_, rwo, rwo, rwo, x2_, x2_, x2_, x, MROWS, CC, CC);
    // 6. h = rmsnorm(x2, g2)  (rounded)
    rmsnorm_k<<<MROWS, 256>>>(x2_, g2, h_);
    // 7. a = relu(h @ wfc)^2  (rounded)
    tfgemm_k<2><<<gemm_ff, 256, GEMM_SMEM>>>(h_, rwfc, rwfc, rwfc, a_, a_, a_, nullptr, MROWS, FF, CC);
    // 8. out = x2 + a @ wpr   (full fp32)
    tfgemm_k<1><<<gemm_cc, 256, GEMM_SMEM>>>(a_, rwpr, rwpr, rwpr, out, out, out, x2_, MROWS, CC, FF);
}